// round 17
// baseline (speedup 1.0000x reference)
#include <cuda_runtime.h>
#include <cstdint>

// ---------------------------------------------------------------------------
// DFine Multiscale Deformable Attention — fused single-kernel version.
//   B=16, Q=300, HIDDEN=256, N_HEADS=8, d=32
//   SPATIAL = (100,100),(50,50),(25,25),(13,13)  -> S=13294
// Output = concat( out[B,Q,256], aw[B,Q,8,16] )  (float32)
//
// Blocks [0,300): tf32 mma projection + softmax + sampling locations,
//                 publishing per-m-tile completion flags.
// Blocks [300,900): bilinear sampling, spin-waiting on their tile's flags.
// Flags are self-resetting (last sample block of each tile zeroes them), so
// the kernel is graph-replayable with no auxiliary reset launch.
// ---------------------------------------------------------------------------

#define NB        16
#define NQ        300
#define NBQ       (NB * NQ)          // 4800
#define HIDDEN    256
#define NHEADS    8
#define PTOT      16
#define NOUT0     (NBQ * HIDDEN)
#define SENC      13294

#define MT      32                   // queries per m-tile
#define NMT     (NBQ / MT)           // 150
#define NPROJ   (NMT * 2)            // 300 proj blocks (2 n-halves)
#define QB      8                    // queries per sample block
#define NSAMP   (NBQ / QB)           // 600 sample blocks
#define NCB     192
#define KC      8
#define NCHUNK  (HIDDEN / KC)        // 32

__device__ float g_loc[NBQ * 256];
__device__ int   g_done[NMT];        // proj completions per tile (target 2)
__device__ int   g_seen[NMT];        // sample passers per tile (target 4)

// ---------------- small PTX helpers ----------------
__device__ __forceinline__ void cp_async16(void* smem_dst, const void* gsrc) {
    unsigned sd = (unsigned)__cvta_generic_to_shared(smem_dst);
    asm volatile("cp.async.ca.shared.global [%0], [%1], 16;" :: "r"(sd), "l"(gsrc));
}
__device__ __forceinline__ void cp_commit() {
    asm volatile("cp.async.commit_group;");
}
template <int N>
__device__ __forceinline__ void cp_wait() {
    asm volatile("cp.async.wait_group %0;" :: "n"(N));
}
__device__ __forceinline__ uint32_t cvt_tf32(float x) {
    uint32_t r; asm("cvt.rna.tf32.f32 %0, %1;" : "=r"(r) : "f"(x)); return r;
}
__device__ __forceinline__ void mma_tf32(float* d, const uint32_t* a, const uint32_t* b) {
    asm("mma.sync.aligned.m16n8k8.row.col.f32.tf32.tf32.f32 "
        "{%0,%1,%2,%3}, {%4,%5,%6,%7}, {%8,%9}, {%0,%1,%2,%3};"
        : "+f"(d[0]), "+f"(d[1]), "+f"(d[2]), "+f"(d[3])
        : "r"(a[0]), "r"(a[1]), "r"(a[2]), "r"(a[3]), "r"(b[0]), "r"(b[1]));
}

struct ProjSmem {
    float A[MT][256];                // XOR-swizzled (col ^= (row&7)<<2)
    float Wst[2][KC][200];           // pad 200 -> conflict-free B frags
};

// ---------------------------------------------------------------------------
// proj role (R13 code)
// ---------------------------------------------------------------------------
__device__ __forceinline__
void proj_role(char* smraw, int pbid,
               const float* __restrict__ hs, const float* __restrict__ ref,
               const float* __restrict__ W_off, const float* __restrict__ b_off,
               const float* __restrict__ W_attn, const float* __restrict__ b_attn,
               float* __restrict__ out_aw)
{
    ProjSmem* ps = reinterpret_cast<ProjSmem*>(smraw);
    float (*C)[NCB] = reinterpret_cast<float (*)[NCB]>(smraw);

    const int tid = threadIdx.x;
    const int w   = tid >> 5;
    const int l   = tid & 31;
    const int mt  = pbid >> 1;
    const int cb  = pbid & 1;
    const int bq0 = mt * MT;

    // ---- load A (32 hs rows) with XOR swizzle ----
    {
        const float4* src = (const float4*)(hs + (size_t)bq0 * 256);
#pragma unroll
        for (int j = 0; j < 8; ++j) {
            const int idx = tid + j * 256;           // 0..2047
            const int r = idx >> 6, c4 = idx & 63;
            const float4 v = __ldg(src + idx);
            const int col = (c4 * 4) ^ ((r & 7) << 2);
            *(float4*)&ps->A[r][col] = v;
        }
    }

    auto issue_chunk = [&](int c, int stg) {
        const int k0 = c * KC;
#pragma unroll
        for (int q = 0; q < 2; ++q) {
            const int f = tid + q * 256;
            if (f < 384) {
                const int kr = f / 48, cf = f % 48;
                const int gc4 = cb * 48 + cf;        // global float4 column
                const float* src = (gc4 < 64)
                    ? (W_off  + (size_t)(k0 + kr) * 256 + gc4 * 4)
                    : (W_attn + (size_t)(k0 + kr) * 128 + (gc4 - 64) * 4);
                cp_async16(&ps->Wst[stg][kr][cf * 4], src);
            }
        }
    };

    float d[6][4];
#pragma unroll
    for (int i = 0; i < 6; ++i)
#pragma unroll
        for (int j = 0; j < 4; ++j) d[i][j] = 0.0f;

    issue_chunk(0, 0);
    cp_commit();

#pragma unroll 1
    for (int c = 0; c < NCHUNK; ++c) {
        if (c + 1 < NCHUNK) issue_chunk(c + 1, (c + 1) & 1);
        cp_commit();
        cp_wait<1>();
        __syncthreads();

        const int stg = c & 1;
        const int k0  = c * KC;

        uint32_t a[2][4];
#pragma unroll
        for (int ms = 0; ms < 2; ++ms) {
            const int r0 = ms * 16 + (l >> 2);
            const int sw = (r0 & 7) << 2;
            const int cA = k0 + (l & 3);
            a[ms][0] = cvt_tf32(ps->A[r0    ][ cA      ^ sw]);
            a[ms][1] = cvt_tf32(ps->A[r0 + 8][ cA      ^ sw]);
            a[ms][2] = cvt_tf32(ps->A[r0    ][(cA + 4) ^ sw]);
            a[ms][3] = cvt_tf32(ps->A[r0 + 8][(cA + 4) ^ sw]);
        }
        uint32_t b[3][2];
#pragma unroll
        for (int ns = 0; ns < 3; ++ns) {
            const int n = w * 24 + ns * 8 + (l >> 2);
            b[ns][0] = cvt_tf32(ps->Wst[stg][ l & 3     ][n]);
            b[ns][1] = cvt_tf32(ps->Wst[stg][(l & 3) + 4][n]);
        }
#pragma unroll
        for (int ms = 0; ms < 2; ++ms)
#pragma unroll
            for (int ns = 0; ns < 3; ++ns)
                mma_tf32(d[ms * 3 + ns], a[ms], b[ns]);

        __syncthreads();
    }

    // ---- write accumulators to C tile (reuses A/Wst memory) ----
#pragma unroll
    for (int ms = 0; ms < 2; ++ms)
#pragma unroll
        for (int ns = 0; ns < 3; ++ns) {
            const int r  = ms * 16 + (l >> 2);
            const int cc = w * 24 + ns * 8 + 2 * (l & 3);
            const float* D = d[ms * 3 + ns];
            C[r    ][cc]     = D[0];
            C[r    ][cc + 1] = D[1];
            C[r + 8][cc]     = D[2];
            C[r + 8][cc + 1] = D[3];
        }
    __syncthreads();

    // ---- epilogue: 192 active threads, one column each ----
    if (tid < NCB) {
        if (cb == 0 || tid < 64) {
            const int col = cb * 192 + tid;
            const float bo = __ldg(b_off + col);
            const int cxy = col & 1;
#pragma unroll 4
            for (int r = 0; r < MT; ++r) {
                const float4 rf = __ldg((const float4*)ref + (bq0 + r));
                const float base = cxy ? rf.y : rf.x;
                const float wh   = cxy ? rf.w : rf.z;
                const float val  = C[r][tid] + bo;
                g_loc[(size_t)(bq0 + r) * 256 + col] = fmaf(val * 0.125f, wh, base);
            }
        } else {
            const int idx = tid - 64;
            const float ba = __ldg(b_attn + idx);
#pragma unroll 2
            for (int r = 0; r < MT; ++r) {
                const float v = C[r][tid] + ba;
                float m = v;
#pragma unroll
                for (int o = 8; o; o >>= 1)
                    m = fmaxf(m, __shfl_xor_sync(0xffffffffu, m, o));
                const float e = __expf(v - m);
                float s = e;
#pragma unroll
                for (int o = 8; o; o >>= 1)
                    s += __shfl_xor_sync(0xffffffffu, s, o);
                out_aw[(size_t)(bq0 + r) * 128 + idx] = e / s;
            }
        }
    }

    // ---- publish completion ----
    __syncthreads();
    if (tid == 0) {
        __threadfence();
        atomicAdd(&g_done[mt], 1);
    }
}

// ---------------------------------------------------------------------------
// sample role (R8 code + flag gate)
// ---------------------------------------------------------------------------
__device__ __forceinline__
void sample_role(char* smraw, int sid,
                 const float* __restrict__ enc,
                 const float* __restrict__ aw,
                 float* __restrict__ out)
{
    int2 (*s_tap)[512] = reinterpret_cast<int2 (*)[512]>(smraw);  // [2][512]

    const int bq0 = sid * QB;
    const int mt  = sid >> 2;        // 4 sample blocks per 32-query tile
    const int tid = threadIdx.x;

    // ---- gate: wait for both proj halves of this tile ----
    if (tid == 0) {
        while (atomicCAS(&g_done[mt], 2, 2) != 2)
            __nanosleep(64);
        __threadfence();
        const int old = atomicAdd(&g_seen[mt], 1);
        if (old == 3) {              // all 4 sample blocks have passed
            atomicExch(&g_done[mt], 0);
            atomicExch(&g_seen[mt], 0);
        }
    }
    __syncthreads();

    const int task0 = tid,        hp0 = task0 >> 2, t0 = task0 & 3;
    const int task1 = tid + 256,  hp1 = task1 >> 2, t1 = task1 & 3;

    const int lvl0 = (hp0 & 15) >> 2, lvl1 = (hp1 & 15) >> 2;
    const int w0_  = (lvl0 == 0) ? 100 : (lvl0 == 1) ? 50 : (lvl0 == 2) ? 25 : 13;
    const int w1_  = (lvl1 == 0) ? 100 : (lvl1 == 1) ? 50 : (lvl1 == 2) ? 25 : 13;
    const int st0  = (lvl0 == 0) ? 0 : (lvl0 == 1) ? 10000 : (lvl0 == 2) ? 12500 : 13125;
    const int st1  = (lvl1 == 0) ? 0 : (lvl1 == 1) ? 10000 : (lvl1 == 2) ? 12500 : 13125;

    const int h    = tid >> 5;
    const int lane = tid & 31;
    const int t    = lane >> 3;
    const int dq   = (lane & 7) << 2;

    auto tap_make = [](int hp, int tp, int w, int st, float2 l2, float a) -> int2 {
        const float x = fmaf(l2.x, (float)w, -0.5f);
        const float y = fmaf(l2.y, (float)w, -0.5f);
        const float x0f = floorf(x), y0f = floorf(y);
        const float wx1 = x - x0f, wy1 = y - y0f;
        const int tx = tp & 1, ty = tp >> 1;
        const int xi = (int)x0f + tx;
        const int yi = (int)y0f + ty;
        const bool valid = (xi >= 0) && (xi < w) && (yi >= 0) && (yi < w);
        const float wt = (ty ? wy1 : 1.0f - wy1) * (tx ? wx1 : 1.0f - wx1) * a;
        const int off = st * 256 + (hp >> 4) * 32 + (yi * w + xi) * 256;
        return make_int2(valid ? off : 0, __float_as_int(valid ? wt : 0.0f));
    };

    {
        float2 l0 = ((const float2*)g_loc)[(size_t)bq0 * 128 + hp0];
        float2 l1 = ((const float2*)g_loc)[(size_t)bq0 * 128 + hp1];
        float  a0 = aw[(size_t)bq0 * 128 + hp0];
        float  a1 = aw[(size_t)bq0 * 128 + hp1];
        s_tap[0][task0] = tap_make(hp0, t0, w0_, st0, l0, a0);
        s_tap[0][task1] = tap_make(hp1, t1, w1_, st1, l1, a1);
    }

#pragma unroll 1
    for (int i = 0; i < QB; ++i) {
        __syncthreads();
        const int bq  = bq0 + i;
        const int buf = i & 1;

        float2 nl0, nl1; float na0, na1;
        if (i + 1 < QB) {
            const int nbq = bq + 1;
            nl0 = ((const float2*)g_loc)[(size_t)nbq * 128 + hp0];
            nl1 = ((const float2*)g_loc)[(size_t)nbq * 128 + hp1];
            na0 = aw[(size_t)nbq * 128 + hp0];
            na1 = aw[(size_t)nbq * 128 + hp1];
        }

        const int b = bq / NQ;
        const float* encb = enc + (size_t)b * (SENC * 256) + dq;
        const int2* tb = &s_tap[buf][h * PTOT * 4 + t];

        float ax = 0.f, ay = 0.f, az = 0.f, aq = 0.f;
#pragma unroll
        for (int pb = 0; pb < PTOT; pb += 8) {
            int   idx[8];
            float wt[8];
#pragma unroll
            for (int j = 0; j < 8; ++j) {
                const int2 tp = tb[(pb + j) * 4];
                idx[j] = tp.x;
                wt[j]  = __int_as_float(tp.y);
            }
            float4 v[8];
#pragma unroll
            for (int j = 0; j < 8; ++j)
                v[j] = __ldg((const float4*)(encb + idx[j]));
#pragma unroll
            for (int j = 0; j < 8; ++j) {
                ax = fmaf(wt[j], v[j].x, ax);
                ay = fmaf(wt[j], v[j].y, ay);
                az = fmaf(wt[j], v[j].z, az);
                aq = fmaf(wt[j], v[j].w, aq);
            }
        }

#pragma unroll
        for (int o = 8; o <= 16; o <<= 1) {
            ax += __shfl_xor_sync(0xffffffffu, ax, o);
            ay += __shfl_xor_sync(0xffffffffu, ay, o);
            az += __shfl_xor_sync(0xffffffffu, az, o);
            aq += __shfl_xor_sync(0xffffffffu, aq, o);
        }
        if (lane < 8) {
            float4 r;
            r.x = ax; r.y = ay; r.z = az; r.w = aq;
            *(float4*)(out + (size_t)bq * 256 + h * 32 + dq) = r;
        }

        if (i + 1 < QB) {
            s_tap[buf ^ 1][task0] = tap_make(hp0, t0, w0_, st0, nl0, na0);
            s_tap[buf ^ 1][task1] = tap_make(hp1, t1, w1_, st1, nl1, na1);
        }
    }
}

// ---------------------------------------------------------------------------
// fused kernel: proj blocks first (guaranteed resident in wave 1 at >=3
// blocks/SM), then spin-gated sample blocks.
// ---------------------------------------------------------------------------
__global__ __launch_bounds__(256, 3)
void dfine_fused_kernel(const float* __restrict__ hs,
                        const float* __restrict__ enc,
                        const float* __restrict__ ref,
                        const float* __restrict__ W_off,
                        const float* __restrict__ b_off,
                        const float* __restrict__ W_attn,
                        const float* __restrict__ b_attn,
                        float* __restrict__ out,
                        float* __restrict__ out_aw)
{
    __shared__ __align__(16) char smraw[sizeof(ProjSmem)];  // 44.5 KB

    if (blockIdx.x < NPROJ) {
        proj_role(smraw, blockIdx.x, hs, ref, W_off, b_off, W_attn, b_attn,
                  out_aw);
    } else {
        sample_role(smraw, blockIdx.x - NPROJ, enc, out_aw, out);
    }
}

// ---------------------------------------------------------------------------
extern "C" void kernel_launch(void* const* d_in, const int* in_sizes, int n_in,
                              void* d_out, int out_size)
{
    const float* hs     = (const float*)d_in[0];   // (B,Q,256)
    const float* enc    = (const float*)d_in[1];   // (B,S,256)
    const float* ref    = (const float*)d_in[2];   // (B,Q,1,4)
    const float* W_off  = (const float*)d_in[3];   // (256,256)
    const float* b_off  = (const float*)d_in[4];   // (256,)
    const float* W_attn = (const float*)d_in[5];   // (256,128)
    const float* b_attn = (const float*)d_in[6];   // (128,)

    float* out    = (float*)d_out;                 // (B,Q,256)
    float* out_aw = (float*)d_out + NOUT0;         // (B,Q,8,16)

    dfine_fused_kernel<<<NPROJ + NSAMP, 256>>>(hs, enc, ref, W_off, b_off,
                                               W_attn, b_attn, out, out_aw);
}